// round 14
// baseline (speedup 1.0000x reference)
#include <cuda_runtime.h>
#include <cuda_fp16.h>
#include <cstdint>

#define BATCH 2
#define TSEQ 2048
#define CEMB 2048
#define NHEAD 16
#define LDIM 128
#define MROWS (BATCH*TSEQ)
#define QSTR (NHEAD*LDIM)   // 2048

// ---------------------------------------------------------------------------
// Scratch (__device__ globals: allocation-free rule). All fp16.
// ---------------------------------------------------------------------------
__device__ __half g_xh[MROWS*CEMB], g_xl[MROWS*CEMB];   // x split
__device__ __half g_qh[MROWS*QSTR], g_ql[MROWS*QSTR];   // q split
__device__ __half g_kh[MROWS*LDIM], g_kl[MROWS*LDIM];   // k split
__device__ __half g_yh[MROWS*QSTR], g_yl[MROWS*QSTR];   // y split
__device__ uint32_t g_wdh[QSTR*(CEMB/2)];               // W_d    fp16 HI pairs
__device__ uint32_t g_wlh[LDIM*(CEMB/2)], g_wll[LDIM*(CEMB/2)];  // W_lat hi/lo
__device__ uint32_t g_wph[CEMB*(QSTR/2)];               // W_proj fp16 HI pairs

// ---------------------------------------------------------------------------
// Helpers
// ---------------------------------------------------------------------------
__device__ __forceinline__ uint32_t smem_u32(const void* p){
    uint32_t a;
    asm("{ .reg .u64 t; cvta.to.shared.u64 t, %1; cvt.u32.u64 %0, t; }"
        : "=r"(a) : "l"(p));
    return a;
}
__device__ __forceinline__ float hfround(float x){
    return __half2float(__float2half_rn(x));
}
__device__ __forceinline__ uint32_t pack2h(float lo, float hi){
    uint32_t r;
    asm("cvt.rn.f16x2.f32 %0, %1, %2;" : "=r"(r) : "f"(hi), "f"(lo));
    return r;
}

#define CP16(dst_u32, src_ptr) \
    asm volatile("cp.async.cg.shared.global [%0], [%1], 16;" \
                 :: "r"(dst_u32), "l"(src_ptr) : "memory")
#define CP_COMMIT() asm volatile("cp.async.commit_group;" ::: "memory")
#define CP_WAIT(n)  asm volatile("cp.async.wait_group %0;" :: "n"(n) : "memory")

#define LDSM4(R, ADDR)                                                        \
    asm volatile("ldmatrix.sync.aligned.m8n8.x4.shared.b16 {%0,%1,%2,%3}, [%4];" \
        : "=r"((R)[0]), "=r"((R)[1]), "=r"((R)[2]), "=r"((R)[3]) : "r"(ADDR))
#define LDSM4T(R, ADDR)                                                       \
    asm volatile("ldmatrix.sync.aligned.m8n8.x4.trans.shared.b16 {%0,%1,%2,%3}, [%4];" \
        : "=r"((R)[0]), "=r"((R)[1]), "=r"((R)[2]), "=r"((R)[3]) : "r"(ADDR))

// NOTE: not volatile — register-only op; lets ptxas schedule around RAW chains.
#define MMA_F16(acc, a, b0, b1)                                               \
    asm("mma.sync.aligned.m16n8k16.row.col.f32.f16.f16.f32 "                  \
        "{%0,%1,%2,%3}, {%4,%5,%6,%7}, {%8,%9}, {%0,%1,%2,%3};"               \
        : "+f"((acc)[0]), "+f"((acc)[1]), "+f"((acc)[2]), "+f"((acc)[3])      \
        : "r"((a)[0]), "r"((a)[1]), "r"((a)[2]), "r"((a)[3]),                 \
          "r"(b0), "r"(b1))

// ---------------------------------------------------------------------------
// Split fp32 -> (hi, lo) fp16
// ---------------------------------------------------------------------------
__global__ void split_rows(const float* __restrict__ src,
                           __half* __restrict__ hi,
                           __half* __restrict__ lo, int n)
{
    int i = (blockIdx.x * 256 + threadIdx.x) * 4;
    if (i >= n) return;
    float4 v = *(const float4*)(src + i);
    *(uint32_t*)(hi + i)     = pack2h(v.x, v.y);
    *(uint32_t*)(hi + i + 2) = pack2h(v.z, v.w);
    *(uint32_t*)(lo + i)     = pack2h(v.x - hfround(v.x), v.y - hfround(v.y));
    *(uint32_t*)(lo + i + 2) = pack2h(v.z - hfround(v.z), v.w - hfround(v.w));
}

// ---------------------------------------------------------------------------
// Combined weight pack: by<64 -> W_d (hi only); by>=64 -> W_lat (hi/lo).
// ---------------------------------------------------------------------------
__global__ void pack_wd_wlat(const float* __restrict__ Wd,
                             uint32_t* __restrict__ wdh,
                             const float* __restrict__ Wlat,
                             uint32_t* __restrict__ wlh,
                             uint32_t* __restrict__ wll)
{
    __shared__ float t[32][33];
    const int k0 = blockIdx.x * 32;
    const int tx = threadIdx.x, ty = threadIdx.y;
    const bool lat = (blockIdx.y >= 64);
    const int n0 = lat ? (blockIdx.y - 64) * 32 : blockIdx.y * 32;
    const float* W = lat ? Wlat : Wd;
    const int N = lat ? LDIM : QSTR;
    for (int i = ty; i < 32; i += 8)
        t[i][tx] = W[(size_t)(k0 + i) * N + n0 + tx];
    __syncthreads();
    if (tx < 16) {
        for (int i = ty; i < 32; i += 8) {
            float v0 = t[2*tx][i], v1 = t[2*tx+1][i];
            size_t o = (size_t)(n0 + i) * (CEMB >> 1) + (k0 >> 1) + tx;
            if (lat) {
                wlh[o] = pack2h(v0, v1);
                wll[o] = pack2h(v0 - hfround(v0), v1 - hfround(v1));
            } else {
                wdh[o] = pack2h(v0, v1);
            }
        }
    }
}

// ---------------------------------------------------------------------------
// Transpose-pack fp16 HI only (W_proj)
// ---------------------------------------------------------------------------
__global__ void split_pack_h(const float* __restrict__ W,
                             uint32_t* __restrict__ hp, int K, int N)
{
    __shared__ float t[32][33];
    const int k0 = blockIdx.x * 32, n0 = blockIdx.y * 32;
    const int tx = threadIdx.x, ty = threadIdx.y;
    for (int i = ty; i < 32; i += 8)
        t[i][tx] = W[(size_t)(k0 + i) * N + n0 + tx];
    __syncthreads();
    if (tx < 16) {
        for (int i = ty; i < 32; i += 8) {
            float v0 = t[2*tx][i], v1 = t[2*tx+1][i];
            hp[(size_t)(n0 + i) * (K >> 1) + (k0 >> 1) + tx] = pack2h(v0, v1);
        }
    }
}

// ---------------------------------------------------------------------------
// Fused q/k GEMM (fp16): q 2-term, latent column 3-term.
// Inner mma ordering: distance-4 RAW chains (all-hi pass, all-lo pass, ...).
// ---------------------------------------------------------------------------
#define SROWB 80
#define REGB  (128*SROWB)
#define OFF_AH 0
#define OFF_AL REGB
#define OFF_BH (2*REGB)
#define OFF_BL (3*REGB)
#define STAGE  (4*REGB)
#define GEMM_SMEM (2*STAGE)

__global__ void __launch_bounds__(256, 2)
gemm_f16qk(const __half* __restrict__ Ah,
           const __half* __restrict__ Al,
           const uint32_t* __restrict__ Bh,
           const float* __restrict__ bias,
           __half* __restrict__ Ch,
           __half* __restrict__ Cl,
           int Ndim, int Kdim,
           const uint32_t* __restrict__ B2h,
           const uint32_t* __restrict__ B2l,
           const float* __restrict__ bias2,
           __half* __restrict__ C2h,
           __half* __restrict__ C2l,
           int N2)
{
    extern __shared__ char sm[];
    const uint32_t smb = smem_u32(sm);
    const int tid = threadIdx.x;
    const int lane = tid & 31, wid = tid >> 5;
    const int warp_row = wid & 3, warp_col = wid >> 2;
    const int m0 = blockIdx.y << 7;
    const int lr = lane >> 2, lc = lane & 3;
    const int KH = Kdim >> 1;

    const uint32_t* pBh = Bh;  const uint32_t* pBl = nullptr;
    const float* pbias = bias;
    __half* pCh = Ch;          __half* pCl = Cl;
    int Nd = Ndim;
    int n0 = blockIdx.x << 7;
    const bool lat3 = (n0 >= Ndim);
    if (lat3) {
        pBh = B2h; pBl = B2l; pbias = bias2; pCh = C2h; pCl = C2l;
        Nd = N2; n0 = 0;
    }

    float acc[2][8][4];
    #pragma unroll
    for (int mt = 0; mt < 2; mt++)
        #pragma unroll
        for (int nt = 0; nt < 8; nt++)
            #pragma unroll
            for (int i = 0; i < 4; i++) acc[mt][nt][i] = 0.f;

    const int crow = tid >> 2, cch = tid & 3;
    const int nk = Kdim >> 5;

    auto issue = [&](int kc) {
        const uint32_t base = smb + (kc & 1) * STAGE;
        const int k0 = kc << 5, kp0 = kc << 4;
        #pragma unroll
        for (int p = 0; p < 2; p++) {
            int row = p * 64 + crow;
            uint32_t d = base + row * SROWB + cch * 16;
            CP16(d + OFF_AH, Ah + (size_t)(m0 + row) * Kdim + k0 + cch * 8);
            CP16(d + OFF_AL, Al + (size_t)(m0 + row) * Kdim + k0 + cch * 8);
            CP16(d + OFF_BH, pBh + (size_t)(n0 + row) * KH + kp0 + cch * 4);
            if (lat3)
                CP16(d + OFF_BL, pBl + (size_t)(n0 + row) * KH + kp0 + cch * 4);
        }
        CP_COMMIT();
    };

    issue(0);
    if (nk > 1) issue(1);

    const int a_row = lane & 15, a_koff = lane & 16;
    const int b_row = (lane & 7) + ((lane & 16) ? 8 : 0);
    const int b_koff = (lane & 8) ? 16 : 0;

    for (int kc = 0; kc < nk; kc++) {
        if (kc + 1 < nk) CP_WAIT(1); else CP_WAIT(0);
        __syncthreads();
        const uint32_t base = smb + (kc & 1) * STAGE;

        #pragma unroll
        for (int ks = 0; ks < 2; ks++) {
            uint32_t ah[2][4], al[2][4];
            #pragma unroll
            for (int mt = 0; mt < 2; mt++) {
                uint32_t aa = base + OFF_AH
                            + (warp_row*32 + mt*16 + a_row) * SROWB
                            + ks*32 + a_koff;
                LDSM4(ah[mt], aa);
                LDSM4(al[mt], aa + (OFF_AL - OFF_AH));
            }
            #pragma unroll
            for (int np = 0; np < 4; np++) {
                uint32_t ba = base + OFF_BH
                            + (warp_col*64 + np*16 + b_row) * SROWB
                            + ks*32 + b_koff;
                uint32_t bh4[4], bl4[4];
                LDSM4(bh4, ba);
                if (lat3) LDSM4(bl4, ba + (OFF_BL - OFF_BH));
                // hi pass (4 independent targets)
                MMA_F16(acc[0][2*np  ], ah[0], bh4[0], bh4[1]);
                MMA_F16(acc[1][2*np  ], ah[1], bh4[0], bh4[1]);
                MMA_F16(acc[0][2*np+1], ah[0], bh4[2], bh4[3]);
                MMA_F16(acc[1][2*np+1], ah[1], bh4[2], bh4[3]);
                // lo pass
                MMA_F16(acc[0][2*np  ], al[0], bh4[0], bh4[1]);
                MMA_F16(acc[1][2*np  ], al[1], bh4[0], bh4[1]);
                MMA_F16(acc[0][2*np+1], al[0], bh4[2], bh4[3]);
                MMA_F16(acc[1][2*np+1], al[1], bh4[2], bh4[3]);
                if (lat3) {
                    MMA_F16(acc[0][2*np  ], ah[0], bl4[0], bl4[1]);
                    MMA_F16(acc[1][2*np  ], ah[1], bl4[0], bl4[1]);
                    MMA_F16(acc[0][2*np+1], ah[0], bl4[2], bl4[3]);
                    MMA_F16(acc[1][2*np+1], ah[1], bl4[2], bl4[3]);
                }
            }
        }
        __syncthreads();
        if (kc + 2 < nk) issue(kc + 2);
    }

    #pragma unroll
    for (int mt = 0; mt < 2; mt++) {
        const int r0 = m0 + warp_row*32 + mt*16 + lr;
        #pragma unroll
        for (int nt = 0; nt < 8; nt++) {
            const int col = n0 + warp_col*64 + nt*8 + lc*2;
            const float2 bv = *(const float2*)(pbias + col);
            float v0 = acc[mt][nt][0] + bv.x, v1 = acc[mt][nt][1] + bv.y;
            float v2 = acc[mt][nt][2] + bv.x, v3 = acc[mt][nt][3] + bv.y;
            *(uint32_t*)(pCh + (size_t)r0 * Nd + col) = pack2h(v0, v1);
            *(uint32_t*)(pCl + (size_t)r0 * Nd + col) =
                pack2h(v0 - hfround(v0), v1 - hfround(v1));
            *(uint32_t*)(pCh + (size_t)(r0+8) * Nd + col) = pack2h(v2, v3);
            *(uint32_t*)(pCl + (size_t)(r0+8) * Nd + col) =
                pack2h(v2 - hfround(v2), v3 - hfround(v3));
        }
    }
}

// ---------------------------------------------------------------------------
// fp16 2-mma proj GEMM, distance-4 mma ordering.
// ---------------------------------------------------------------------------
#define F_OFF_AH 0
#define F_OFF_AL REGB
#define F_OFF_BH (2*REGB)
#define F_STAGE  (3*REGB)
#define GEMM_SMEM_F16 (2*F_STAGE)

__global__ void __launch_bounds__(256, 2)
gemm_f16x2(const __half* __restrict__ Ah,
           const __half* __restrict__ Al,
           const uint32_t* __restrict__ Bh,
           const float* __restrict__ bias,
           float* __restrict__ C,
           int Ndim, int Kdim)
{
    extern __shared__ char sm[];
    const uint32_t smb = smem_u32(sm);
    const int tid = threadIdx.x;
    const int lane = tid & 31, wid = tid >> 5;
    const int warp_row = wid & 3, warp_col = wid >> 2;
    const int m0 = blockIdx.y << 7, n0 = blockIdx.x << 7;
    const int lr = lane >> 2, lc = lane & 3;
    const int KH = Kdim >> 1;

    float acc[2][8][4];
    #pragma unroll
    for (int mt = 0; mt < 2; mt++)
        #pragma unroll
        for (int nt = 0; nt < 8; nt++)
            #pragma unroll
            for (int i = 0; i < 4; i++) acc[mt][nt][i] = 0.f;

    const int crow = tid >> 2, cch = tid & 3;
    const int nk = Kdim >> 5;

    auto issue = [&](int kc) {
        const uint32_t base = smb + (kc & 1) * F_STAGE;
        const int k0 = kc << 5, kp0 = kc << 4;
        #pragma unroll
        for (int p = 0; p < 2; p++) {
            int row = p * 64 + crow;
            uint32_t d = base + row * SROWB + cch * 16;
            CP16(d + F_OFF_AH, Ah + (size_t)(m0 + row) * Kdim + k0 + cch * 8);
            CP16(d + F_OFF_AL, Al + (size_t)(m0 + row) * Kdim + k0 + cch * 8);
            CP16(d + F_OFF_BH, Bh + (size_t)(n0 + row) * KH + kp0 + cch * 4);
        }
        CP_COMMIT();
    };

    issue(0);
    if (nk > 1) issue(1);

    const int a_row = lane & 15, a_koff = lane & 16;
    const int b_row = (lane & 7) + ((lane & 16) ? 8 : 0);
    const int b_koff = (lane & 8) ? 16 : 0;

    for (int kc = 0; kc < nk; kc++) {
        if (kc + 1 < nk) CP_WAIT(1); else CP_WAIT(0);
        __syncthreads();
        const uint32_t base = smb + (kc & 1) * F_STAGE;

        #pragma unroll
        for (int ks = 0; ks < 2; ks++) {
            uint32_t ah[2][4], al[2][4];
            #pragma unroll
            for (int mt = 0; mt < 2; mt++) {
                uint32_t aa = base + F_OFF_AH
                            + (warp_row*32 + mt*16 + a_row) * SROWB
                            + ks*32 + a_koff;
                LDSM4(ah[mt], aa);
                LDSM4(al[mt], aa + (F_OFF_AL - F_OFF_AH));
            }
            #pragma unroll
            for (int np = 0; np < 4; np++) {
                uint32_t ba = base + F_OFF_BH
                            + (warp_col*64 + np*16 + b_row) * SROWB
                            + ks*32 + b_koff;
                uint32_t bh4[4];
                LDSM4(bh4, ba);
                MMA_F16(acc[0][2*np  ], ah[0], bh4[0], bh4[1]);
                MMA_F16(acc[1][2*np  ], ah[1], bh4[0], bh4[1]);
                MMA_F16(acc[0][2*np+1], ah[0], bh4[2], bh4[3]);
                MMA_F16(acc[1][2*np+1], ah[1], bh4[2], bh4[3]);
                MMA_F16(acc[0][2*np  ], al[0], bh4[0], bh4[1]);
                MMA_F16(acc[1][2*np  ], al[1], bh4[0], bh4[1]);
                MMA_F16(acc[0][2*np+1], al[0], bh4[2], bh4[3]);
                MMA_F16(acc[1][2*np+1], al[1], bh4[2], bh4[3]);
            }
        }
        __syncthreads();
        if (kc + 2 < nk) issue(kc + 2);
    }

    #pragma unroll
    for (int mt = 0; mt < 2; mt++) {
        const int r0 = m0 + warp_row*32 + mt*16 + lr;
        #pragma unroll
        for (int nt = 0; nt < 8; nt++) {
            const int col = n0 + warp_col*64 + nt*8 + lc*2;
            const float2 bv = *(const float2*)(bias + col);
            *(float2*)(C + (size_t)r0 * Ndim + col) =
                make_float2(acc[mt][nt][0] + bv.x, acc[mt][nt][1] + bv.y);
            *(float2*)(C + (size_t)(r0+8) * Ndim + col) =
                make_float2(acc[mt][nt][2] + bv.x, acc[mt][nt][3] + bv.y);
        }
    }
}

// ---------------------------------------------------------------------------
// Attention (R10 structure: s-tile 64, persistent Q frags, 1 CTA/SM)
// with distance-4 mma ordering in S and Y passes.
// ---------------------------------------------------------------------------
#define KROWB 272
#define STG_L (64*KROWB)
#define STAGE_A (2*64*KROWB)
#define Q_OFF (2*STAGE_A)
#define ATTN_SMEM (2*STAGE_A + 128*KROWB)

__global__ void __launch_bounds__(256, 1)
attn_kernel(const __half* __restrict__ qh,
            const __half* __restrict__ ql,
            const __half* __restrict__ kh,
            const __half* __restrict__ kl,
            __half* __restrict__ yh,
            __half* __restrict__ yl)
{
    extern __shared__ char sm[];
    const uint32_t smb = smem_u32(sm);
    const int tid = threadIdx.x;
    const int lane = tid & 31, w = tid >> 5;
    const int lr = lane >> 2, lc = lane & 3;
    const int qt = (int)gridDim.x - 1 - (int)blockIdx.x;   // heavy first
    const int bhid = blockIdx.y;
    const int b = bhid >> 4, h = bhid & 15;

    const char* qbh = (const char*)(qh + ((size_t)b*TSEQ + qt*128)*QSTR + h*LDIM);
    const char* qbl = (const char*)(ql + ((size_t)b*TSEQ + qt*128)*QSTR + h*LDIM);
    const char* kbh = (const char*)(kh + (size_t)b*TSEQ*LDIM);
    const char* kbl = (const char*)(kl + (size_t)b*TSEQ*LDIM);

    uint32_t qfh[8][4], qfl[8][4];
    {
        const int qrow = tid >> 4, qch = tid & 15;
        #pragma unroll
        for (int p = 0; p < 8; p++) {
            int row = p*16 + qrow;
            CP16(smb + Q_OFF + row*KROWB + qch*16, qbh + (size_t)row*QSTR*2 + qch*16);
        }
        CP_COMMIT(); CP_WAIT(0); __syncthreads();
        #pragma unroll
        for (int ks = 0; ks < 8; ks++) {
            uint32_t a = smb + Q_OFF + (w*16 + (lane & 15))*KROWB + ks*32 + (lane & 16);
            LDSM4(qfh[ks], a);
        }
        __syncthreads();
        #pragma unroll
        for (int p = 0; p < 8; p++) {
            int row = p*16 + qrow;
            CP16(smb + Q_OFF + row*KROWB + qch*16, qbl + (size_t)row*QSTR*2 + qch*16);
        }
        CP_COMMIT(); CP_WAIT(0); __syncthreads();
        #pragma unroll
        for (int ks = 0; ks < 8; ks++) {
            uint32_t a = smb + Q_OFF + (w*16 + (lane & 15))*KROWB + ks*32 + (lane & 16);
            LDSM4(qfl[ks], a);
        }
        __syncthreads();
    }

    float yacc[16][4];
    #pragma unroll
    for (int nt = 0; nt < 16; nt++)
        #pragma unroll
        for (int i = 0; i < 4; i++) yacc[nt][i] = 0.f;
    float m0 = -1e30f, m1 = -1e30f, l0 = 0.f, l1 = 0.f;

    const int nkt = 2*qt + 2;
    const int krow = tid >> 4, kch = tid & 15;

    auto issueK = [&](int kt) {
        const uint32_t base = smb + (kt & 1) * STAGE_A;
        #pragma unroll
        for (int p = 0; p < 4; p++) {
            int row = p*16 + krow;
            uint32_t d = base + row*KROWB + kch*16;
            CP16(d,         kbh + (size_t)(kt*64 + row)*256 + kch*16);
            CP16(d + STG_L, kbl + (size_t)(kt*64 + row)*256 + kch*16);
        }
        CP_COMMIT();
    };

    issueK(0);
    if (nkt > 1) issueK(1);

    const float scale = 0.08838834764831845f;
    const int t0g = qt*128 + w*16 + lr, t1g = t0g + 8;
    const int wmax = qt*128 + w*16 + 15;

    for (int kt = 0; kt < nkt; kt++) {
        if (kt + 1 < nkt) CP_WAIT(1); else CP_WAIT(0);
        __syncthreads();
        const uint32_t base = smb + (kt & 1) * STAGE_A;
        const bool diagband = (kt >= 2*qt);
        const bool wskip = diagband && (kt*64 > wmax);

        if (!wskip) {
            float sacc[8][4];
            #pragma unroll
            for (int nt = 0; nt < 8; nt++)
                #pragma unroll
                for (int i = 0; i < 4; i++) sacc[nt][i] = 0.f;

            const int sb_row = (lane & 7) + ((lane & 16) ? 8 : 0);
            const int sb_koff = (lane & 8) ? 16 : 0;
            // np-pairs: 4 LDSM up front, 12 mma over 4 targets (distance 4)
            #pragma unroll
            for (int npp = 0; npp < 2; npp++) {
                if (diagband && kt*64 + npp*32 > wmax) break;
                #pragma unroll
                for (int ks = 0; ks < 8; ks++) {
                    uint32_t ba0 = base + (npp*32 + sb_row)*KROWB + ks*32 + sb_koff;
                    uint32_t ba1 = ba0 + 16*KROWB;
                    uint32_t bhA[4], blA[4], bhB[4], blB[4];
                    LDSM4(bhA, ba0); LDSM4(blA, ba0 + STG_L);
                    LDSM4(bhB, ba1); LDSM4(blB, ba1 + STG_L);
                    float* t0 = sacc[4*npp+0]; float* t1 = sacc[4*npp+1];
                    float* t2 = sacc[4*npp+2]; float* t3 = sacc[4*npp+3];
                    MMA_F16(t0, qfh[ks], bhA[0], bhA[1]);
                    MMA_F16(t1, qfh[ks], bhA[2], bhA[3]);
                    MMA_F16(t2, qfh[ks], bhB[0], bhB[1]);
                    MMA_F16(t3, qfh[ks], bhB[2], bhB[3]);
                    MMA_F16(t0, qfl[ks], bhA[0], bhA[1]);
                    MMA_F16(t1, qfl[ks], bhA[2], bhA[3]);
                    MMA_F16(t2, qfl[ks], bhB[0], bhB[1]);
                    MMA_F16(t3, qfl[ks], bhB[2], bhB[3]);
                    MMA_F16(t0, qfh[ks], blA[0], blA[1]);
                    MMA_F16(t1, qfh[ks], blA[2], blA[3]);
                    MMA_F16(t2, qfh[ks], blB[0], blB[1]);
                    MMA_F16(t3, qfh[ks], blB[2], blB[3]);
                }
            }

            #pragma unroll
            for (int nt = 0; nt < 8; nt++)
                #pragma unroll
                for (int i = 0; i < 4; i++) sacc[nt][i] *= scale;
            if (diagband) {
                #pragma unroll
                for (int nt = 0; nt < 8; nt++) {
                    int s0 = kt*64 + nt*8 + 2*lc;
                    if (s0     > t0g) sacc[nt][0] = -1e30f;
                    if (s0 + 1 > t0g) sacc[nt][1] = -1e30f;
                    if (s0     > t1g) sacc[nt][2] = -1e30f;
                    if (s0 + 1 > t1g) sacc[nt][3] = -1e30f;
                }
            }

            float mx0 = -1e30f, mx1 = -1e30f;
            #pragma unroll
            for (int nt = 0; nt < 8; nt++) {
                mx0 = fmaxf(mx0, fmaxf(sacc[nt][0], sacc[nt][1]));
                mx1 = fmaxf(mx1, fmaxf(sacc[nt][2], sacc[nt][3]));
            }
            mx0 = fmaxf(mx0, __shfl_xor_sync(0xffffffffu, mx0, 1));
            mx0 = fmaxf(mx0, __shfl_xor_sync(0xffffffffu, mx0, 2));
            mx1 = fmaxf(mx1, __shfl_xor_sync(0xffffffffu, mx1, 1));
            mx1 = fmaxf(mx1, __shfl_xor_sync(0xffffffffu, mx1, 2));
            float m0n = fmaxf(m0, mx0), m1n = fmaxf(m1, mx1);
            float c0 = __expf(m0 - m0n), c1 = __expf(m1 - m1n);
            float s0sum = 0.f, s1sum = 0.f;
            #pragma unroll
            for (int nt = 0; nt < 8; nt++) {
                float p0 = __expf(sacc[nt][0] - m0n);
                float p1 = __expf(sacc[nt][1] - m0n);
                float p2 = __expf(sacc[nt][2] - m1n);
                float p3 = __expf(sacc[nt][3] - m1n);
                s0sum += p0 + p1; s1sum += p2 + p3;
                sacc[nt][0] = p0; sacc[nt][1] = p1;
                sacc[nt][2] = p2; sacc[nt][3] = p3;
            }
            s0sum += __shfl_xor_sync(0xffffffffu, s0sum, 1);
            s0sum += __shfl_xor_sync(0xffffffffu, s0sum, 2);
            s1sum += __shfl_xor_sync(0xffffffffu, s1sum, 1);
            s1sum += __shfl_xor_sync(0xffffffffu, s1sum, 2);
            l0 = l0*c0 + s0sum; l1 = l1*c1 + s1sum;
            m0 = m0n; m1 = m1n;
            #pragma unroll
            for (int nt = 0; nt < 16; nt++) {
                yacc[nt][0] *= c0; yacc[nt][1] *= c0;
                yacc[nt][2] *= c1; yacc[nt][3] *= c1;
            }

            // P fragments fp16 hi/lo
            uint32_t pah[4][4], pal[4][4];
            #pragma unroll
            for (int ks2 = 0; ks2 < 4; ks2++) {
                float p0 = sacc[2*ks2][0], p1 = sacc[2*ks2][1];
                float p2 = sacc[2*ks2][2], p3 = sacc[2*ks2][3];
                float q0 = sacc[2*ks2+1][0], q1 = sacc[2*ks2+1][1];
                float q2 = sacc[2*ks2+1][2], q3 = sacc[2*ks2+1][3];
                pah[ks2][0] = pack2h(p0, p1); pah[ks2][1] = pack2h(p2, p3);
                pah[ks2][2] = pack2h(q0, q1); pah[ks2][3] = pack2h(q2, q3);
                pal[ks2][0] = pack2h(p0 - hfround(p0), p1 - hfround(p1));
                pal[ks2][1] = pack2h(p2 - hfround(p2), p3 - hfround(p3));
                pal[ks2][2] = pack2h(q0 - hfround(q0), q1 - hfround(q1));
                pal[ks2][3] = pack2h(q2 - hfround(q2), q3 - hfround(q3));
            }

            // Y += P K : np-pairs, 8 mma over 4 targets (distance 4)
            #pragma unroll
            for (int ks2 = 0; ks2 < 4; ks2++) {
                if (diagband && kt*64 + ks2*16 > wmax) break;
                #pragma unroll
                for (int npp = 0; npp < 4; npp++) {
                    uint32_t va0 = base + (ks2*16 + (lane & 15))*KROWB
                                 + (2*npp)*32 + (lane & 16);
                    uint32_t vA[4], vB[4];
                    LDSM4T(vA, va0);
                    LDSM4T(vB, va0 + 32);
                    float* t0 = yacc[4*npp+0]; float* t1 = yacc[4*npp+1];
                    float* t2 = yacc[4*npp+2]; float* t3 = yacc[4*npp+3];
                    MMA_F16(t0, pah[ks2], vA[0], vA[1]);
                    MMA_F16(t1, pah[ks2], vA[2], vA[3]);
                    MMA_F16(t2, pah[ks2], vB[0], vB[1]);
                    MMA_F16(t3, pah[ks2], vB[2], vB[3]);
                    MMA_F16(t0, pal[ks2], vA[0], vA[1]);
                    MMA_F16(t1, pal[ks2], vA[2], vA[3]);
                    MMA_F16(t2, pal[ks2], vB[0], vB[1]);
                    MMA_F16(t3, pal[ks2], vB[2], vB[3]);
                }
            }
        }
        __syncthreads();
        if (kt + 2 < nkt) issueK(kt + 2);
    }

    const float li0 = 1.0f / l0, li1 = 1.0f / l1;
    #pragma unroll
    for (int nt = 0; nt < 16; nt++) {
        float v0 = yacc[nt][0]*li0, v1 = yacc[nt][1]*li0;
        float v2 = yacc[nt][2]*li1, v3 = yacc[nt][3]*li1;
        size_t o0 = ((size_t)b*TSEQ + t0g)*QSTR + h*LDIM + nt*8 + 2*lc;
        size_t o1 = o0 + (size_t)8*QSTR;
        *(uint32_t*)(yh + o0) = pack2h(v0, v1);
        *(uint32_t*)(yl + o0) = pack2h(v0 - hfround(v0), v1 - hfround(v1));
        *(uint32_t*)(yh + o1) = pack2h(v2, v3);
        *(uint32_t*)(yl + o1) = pack2h(v2 - hfround(v2), v3 - hfround(v3));
    }
}

// ---------------------------------------------------------------------------
extern "C" void kernel_launch(void* const* d_in, const int* in_sizes, int n_in,
                              void* d_out, int out_size)
{
    const float* x      = (const float*)d_in[0];
    const float* W_lat  = (const float*)d_in[1];
    const float* b_lat  = (const float*)d_in[2];
    const float* W_d    = (const float*)d_in[3];
    const float* b_d    = (const float*)d_in[4];
    const float* W_proj = (const float*)d_in[5];
    const float* b_proj = (const float*)d_in[6];
    float* out = (float*)d_out;

    __half *xh, *xl, *qhp, *qlp, *khp, *klp, *yhp, *ylp;
    uint32_t *wdh, *wph, *wlh, *wll;
    cudaGetSymbolAddress((void**)&xh,  g_xh);
    cudaGetSymbolAddress((void**)&xl,  g_xl);
    cudaGetSymbolAddress((void**)&qhp, g_qh);
    cudaGetSymbolAddress((void**)&qlp, g_ql);
    cudaGetSymbolAddress((void**)&khp, g_kh);
    cudaGetSymbolAddress((void**)&klp, g_kl);
    cudaGetSymbolAddress((void**)&yhp, g_yh);
    cudaGetSymbolAddress((void**)&ylp, g_yl);
    cudaGetSymbolAddress((void**)&wdh, g_wdh);
    cudaGetSymbolAddress((void**)&wph, g_wph);
    cudaGetSymbolAddress((void**)&wlh, g_wlh);
    cudaGetSymbolAddress((void**)&wll, g_wll);

    cudaFuncSetAttribute((const void*)gemm_f16qk,
                         cudaFuncAttributeMaxDynamicSharedMemorySize, GEMM_SMEM);
    cudaFuncSetAttribute((const void*)gemm_f16x2,
                         cudaFuncAttributeMaxDynamicSharedMemorySize, GEMM_SMEM_F16);
    cudaFuncSetAttribute((const void*)attn_kernel,
                         cudaFuncAttributeMaxDynamicSharedMemorySize, ATTN_SMEM);

    dim3 tb(32, 8);
    // 0) split x -> fp16 hi/lo
    split_rows<<<(MROWS*CEMB/4 + 255)/256, 256>>>(x, xh, xl, MROWS*CEMB);
    // 1) combined pack: W_d (hi) + W_lat (hi/lo)
    pack_wd_wlat<<<dim3(CEMB/32, 64 + LDIM/32), tb>>>(W_d, wdh, W_lat, wlh, wll);
    // 2) fused q (2-term) + k (3-term) GEMM
    gemm_f16qk<<<dim3(QSTR/128 + 1, MROWS/128), 256, GEMM_SMEM>>>(
        xh, xl, wdh, b_d, qhp, qlp, QSTR, CEMB,
        wlh, wll, b_lat, khp, klp, LDIM);
    // 3) attention (R10 structure + reordered mma)   <-- ncu-profiled slot
    attn_kernel<<<dim3(TSEQ/128, BATCH*NHEAD), 256, ATTN_SMEM>>>(
        qhp, qlp, khp, klp, yhp, ylp);
    // 4) pack W_proj (fp16 hi only)
    split_pack_h<<<dim3(QSTR/32, CEMB/32), tb>>>(W_proj, wph, QSTR, CEMB);
    // 5) out = y @ W_proj + b_proj
    gemm_f16x2<<<dim3(CEMB/128, MROWS/128), 256, GEMM_SMEM_F16>>>(
        yhp, ylp, wph, b_proj, out, CEMB, CEMB);
}

// round 16
// speedup vs baseline: 1.5413x; 1.5413x over previous
#include <cuda_runtime.h>
#include <cuda_fp16.h>
#include <cstdint>

#define BATCH 2
#define TSEQ 2048
#define CEMB 2048
#define NHEAD 16
#define LDIM 128
#define MROWS (BATCH*TSEQ)
#define QSTR (NHEAD*LDIM)   // 2048

// ---------------------------------------------------------------------------
// Scratch (__device__ globals: allocation-free rule). All fp16.
// ---------------------------------------------------------------------------
__device__ __half g_xh[MROWS*CEMB], g_xl[MROWS*CEMB];   // x split
__device__ __half g_qh[MROWS*QSTR], g_ql[MROWS*QSTR];   // q split
__device__ __half g_kh[MROWS*LDIM], g_kl[MROWS*LDIM];   // k split
__device__ __half g_yh[MROWS*QSTR], g_yl[MROWS*QSTR];   // y split
__device__ uint32_t g_wdh[QSTR*(CEMB/2)];               // W_d    fp16 HI pairs
__device__ uint32_t g_wlh[LDIM*(CEMB/2)], g_wll[LDIM*(CEMB/2)];  // W_lat hi/lo
__device__ uint32_t g_wph[CEMB*(QSTR/2)];               // W_proj fp16 HI pairs

// ---------------------------------------------------------------------------
// Helpers
// ---------------------------------------------------------------------------
__device__ __forceinline__ uint32_t smem_u32(const void* p){
    uint32_t a;
    asm("{ .reg .u64 t; cvta.to.shared.u64 t, %1; cvt.u32.u64 %0, t; }"
        : "=r"(a) : "l"(p));
    return a;
}
__device__ __forceinline__ float hfround(float x){
    return __half2float(__float2half_rn(x));
}
__device__ __forceinline__ uint32_t pack2h(float lo, float hi){
    uint32_t r;
    asm("cvt.rn.f16x2.f32 %0, %1, %2;" : "=r"(r) : "f"(hi), "f"(lo));
    return r;
}

#define CP16(dst_u32, src_ptr) \
    asm volatile("cp.async.cg.shared.global [%0], [%1], 16;" \
                 :: "r"(dst_u32), "l"(src_ptr) : "memory")
#define CP_COMMIT() asm volatile("cp.async.commit_group;" ::: "memory")
#define CP_WAIT(n)  asm volatile("cp.async.wait_group %0;" :: "n"(n) : "memory")

#define LDSM4(R, ADDR)                                                        \
    asm volatile("ldmatrix.sync.aligned.m8n8.x4.shared.b16 {%0,%1,%2,%3}, [%4];" \
        : "=r"((R)[0]), "=r"((R)[1]), "=r"((R)[2]), "=r"((R)[3]) : "r"(ADDR))
#define LDSM4T(R, ADDR)                                                       \
    asm volatile("ldmatrix.sync.aligned.m8n8.x4.trans.shared.b16 {%0,%1,%2,%3}, [%4];" \
        : "=r"((R)[0]), "=r"((R)[1]), "=r"((R)[2]), "=r"((R)[3]) : "r"(ADDR))

// volatile is load-bearing: keeps ptxas from stretching live ranges (R14 blew
// regs 128->231 without it). Scheduling freedom comes from statement order.
#define MMA_F16(acc, a, b0, b1)                                               \
    asm volatile(                                                             \
        "mma.sync.aligned.m16n8k16.row.col.f32.f16.f16.f32 "                  \
        "{%0,%1,%2,%3}, {%4,%5,%6,%7}, {%8,%9}, {%0,%1,%2,%3};"               \
        : "+f"((acc)[0]), "+f"((acc)[1]), "+f"((acc)[2]), "+f"((acc)[3])      \
        : "r"((a)[0]), "r"((a)[1]), "r"((a)[2]), "r"((a)[3]),                 \
          "r"(b0), "r"(b1))

// ---------------------------------------------------------------------------
// Split fp32 -> (hi, lo) fp16
// ---------------------------------------------------------------------------
__global__ void split_rows(const float* __restrict__ src,
                           __half* __restrict__ hi,
                           __half* __restrict__ lo, int n)
{
    int i = (blockIdx.x * 256 + threadIdx.x) * 4;
    if (i >= n) return;
    float4 v = *(const float4*)(src + i);
    *(uint32_t*)(hi + i)     = pack2h(v.x, v.y);
    *(uint32_t*)(hi + i + 2) = pack2h(v.z, v.w);
    *(uint32_t*)(lo + i)     = pack2h(v.x - hfround(v.x), v.y - hfround(v.y));
    *(uint32_t*)(lo + i + 2) = pack2h(v.z - hfround(v.z), v.w - hfround(v.w));
}

// ---------------------------------------------------------------------------
// Combined weight pack: by<64 -> W_d (hi only); by>=64 -> W_lat (hi/lo).
// ---------------------------------------------------------------------------
__global__ void pack_wd_wlat(const float* __restrict__ Wd,
                             uint32_t* __restrict__ wdh,
                             const float* __restrict__ Wlat,
                             uint32_t* __restrict__ wlh,
                             uint32_t* __restrict__ wll)
{
    __shared__ float t[32][33];
    const int k0 = blockIdx.x * 32;
    const int tx = threadIdx.x, ty = threadIdx.y;
    const bool lat = (blockIdx.y >= 64);
    const int n0 = lat ? (blockIdx.y - 64) * 32 : blockIdx.y * 32;
    const float* W = lat ? Wlat : Wd;
    const int N = lat ? LDIM : QSTR;
    for (int i = ty; i < 32; i += 8)
        t[i][tx] = W[(size_t)(k0 + i) * N + n0 + tx];
    __syncthreads();
    if (tx < 16) {
        for (int i = ty; i < 32; i += 8) {
            float v0 = t[2*tx][i], v1 = t[2*tx+1][i];
            size_t o = (size_t)(n0 + i) * (CEMB >> 1) + (k0 >> 1) + tx;
            if (lat) {
                wlh[o] = pack2h(v0, v1);
                wll[o] = pack2h(v0 - hfround(v0), v1 - hfround(v1));
            } else {
                wdh[o] = pack2h(v0, v1);
            }
        }
    }
}

// ---------------------------------------------------------------------------
// Transpose-pack fp16 HI only (W_proj)
// ---------------------------------------------------------------------------
__global__ void split_pack_h(const float* __restrict__ W,
                             uint32_t* __restrict__ hp, int K, int N)
{
    __shared__ float t[32][33];
    const int k0 = blockIdx.x * 32, n0 = blockIdx.y * 32;
    const int tx = threadIdx.x, ty = threadIdx.y;
    for (int i = ty; i < 32; i += 8)
        t[i][tx] = W[(size_t)(k0 + i) * N + n0 + tx];
    __syncthreads();
    if (tx < 16) {
        for (int i = ty; i < 32; i += 8) {
            float v0 = t[2*tx][i], v1 = t[2*tx+1][i];
            hp[(size_t)(n0 + i) * (K >> 1) + (k0 >> 1) + tx] = pack2h(v0, v1);
        }
    }
}

// ---------------------------------------------------------------------------
// Fused q/k GEMM (fp16): q 2-term, latent column 3-term.
// R10 structure; mma statements interleaved across 4 targets (distance 4).
// ---------------------------------------------------------------------------
#define SROWB 80
#define REGB  (128*SROWB)
#define OFF_AH 0
#define OFF_AL REGB
#define OFF_BH (2*REGB)
#define OFF_BL (3*REGB)
#define STAGE  (4*REGB)
#define GEMM_SMEM (2*STAGE)

__global__ void __launch_bounds__(256, 2)
gemm_f16qk(const __half* __restrict__ Ah,
           const __half* __restrict__ Al,
           const uint32_t* __restrict__ Bh,
           const float* __restrict__ bias,
           __half* __restrict__ Ch,
           __half* __restrict__ Cl,
           int Ndim, int Kdim,
           const uint32_t* __restrict__ B2h,
           const uint32_t* __restrict__ B2l,
           const float* __restrict__ bias2,
           __half* __restrict__ C2h,
           __half* __restrict__ C2l,
           int N2)
{
    extern __shared__ char sm[];
    const uint32_t smb = smem_u32(sm);
    const int tid = threadIdx.x;
    const int lane = tid & 31, wid = tid >> 5;
    const int warp_row = wid & 3, warp_col = wid >> 2;
    const int m0 = blockIdx.y << 7;
    const int lr = lane >> 2, lc = lane & 3;
    const int KH = Kdim >> 1;

    const uint32_t* pBh = Bh;  const uint32_t* pBl = nullptr;
    const float* pbias = bias;
    __half* pCh = Ch;          __half* pCl = Cl;
    int Nd = Ndim;
    int n0 = blockIdx.x << 7;
    const bool lat3 = (n0 >= Ndim);
    if (lat3) {
        pBh = B2h; pBl = B2l; pbias = bias2; pCh = C2h; pCl = C2l;
        Nd = N2; n0 = 0;
    }

    float acc[2][8][4];
    #pragma unroll
    for (int mt = 0; mt < 2; mt++)
        #pragma unroll
        for (int nt = 0; nt < 8; nt++)
            #pragma unroll
            for (int i = 0; i < 4; i++) acc[mt][nt][i] = 0.f;

    const int crow = tid >> 2, cch = tid & 3;
    const int nk = Kdim >> 5;

    auto issue = [&](int kc) {
        const uint32_t base = smb + (kc & 1) * STAGE;
        const int k0 = kc << 5, kp0 = kc << 4;
        #pragma unroll
        for (int p = 0; p < 2; p++) {
            int row = p * 64 + crow;
            uint32_t d = base + row * SROWB + cch * 16;
            CP16(d + OFF_AH, Ah + (size_t)(m0 + row) * Kdim + k0 + cch * 8);
            CP16(d + OFF_AL, Al + (size_t)(m0 + row) * Kdim + k0 + cch * 8);
            CP16(d + OFF_BH, pBh + (size_t)(n0 + row) * KH + kp0 + cch * 4);
            if (lat3)
                CP16(d + OFF_BL, pBl + (size_t)(n0 + row) * KH + kp0 + cch * 4);
        }
        CP_COMMIT();
    };

    issue(0);
    if (nk > 1) issue(1);

    const int a_row = lane & 15, a_koff = lane & 16;
    const int b_row = (lane & 7) + ((lane & 16) ? 8 : 0);
    const int b_koff = (lane & 8) ? 16 : 0;

    for (int kc = 0; kc < nk; kc++) {
        if (kc + 1 < nk) CP_WAIT(1); else CP_WAIT(0);
        __syncthreads();
        const uint32_t base = smb + (kc & 1) * STAGE;

        #pragma unroll
        for (int ks = 0; ks < 2; ks++) {
            uint32_t ah[2][4], al[2][4];
            #pragma unroll
            for (int mt = 0; mt < 2; mt++) {
                uint32_t aa = base + OFF_AH
                            + (warp_row*32 + mt*16 + a_row) * SROWB
                            + ks*32 + a_koff;
                LDSM4(ah[mt], aa);
                LDSM4(al[mt], aa + (OFF_AL - OFF_AH));
            }
            #pragma unroll
            for (int np = 0; np < 4; np++) {
                uint32_t ba = base + OFF_BH
                            + (warp_col*64 + np*16 + b_row) * SROWB
                            + ks*32 + b_koff;
                uint32_t bh4[4], bl4[4];
                LDSM4(bh4, ba);
                if (lat3) LDSM4(bl4, ba + (OFF_BL - OFF_BH));
                // distance-4 interleave: 4 targets per pass
                MMA_F16(acc[0][2*np  ], ah[0], bh4[0], bh4[1]);
                MMA_F16(acc[1][2*np  ], ah[1], bh4[0], bh4[1]);
                MMA_F16(acc[0][2*np+1], ah[0], bh4[2], bh4[3]);
                MMA_F16(acc[1][2*np+1], ah[1], bh4[2], bh4[3]);
                MMA_F16(acc[0][2*np  ], al[0], bh4[0], bh4[1]);
                MMA_F16(acc[1][2*np  ], al[1], bh4[0], bh4[1]);
                MMA_F16(acc[0][2*np+1], al[0], bh4[2], bh4[3]);
                MMA_F16(acc[1][2*np+1], al[1], bh4[2], bh4[3]);
                if (lat3) {
                    MMA_F16(acc[0][2*np  ], ah[0], bl4[0], bl4[1]);
                    MMA_F16(acc[1][2*np  ], ah[1], bl4[0], bl4[1]);
                    MMA_F16(acc[0][2*np+1], ah[0], bl4[2], bl4[3]);
                    MMA_F16(acc[1][2*np+1], ah[1], bl4[2], bl4[3]);
                }
            }
        }
        __syncthreads();
        if (kc + 2 < nk) issue(kc + 2);
    }

    #pragma unroll
    for (int mt = 0; mt < 2; mt++) {
        const int r0 = m0 + warp_row*32 + mt*16 + lr;
        #pragma unroll
        for (int nt = 0; nt < 8; nt++) {
            const int col = n0 + warp_col*64 + nt*8 + lc*2;
            const float2 bv = *(const float2*)(pbias + col);
            float v0 = acc[mt][nt][0] + bv.x, v1 = acc[mt][nt][1] + bv.y;
            float v2 = acc[mt][nt][2] + bv.x, v3 = acc[mt][nt][3] + bv.y;
            *(uint32_t*)(pCh + (size_t)r0 * Nd + col) = pack2h(v0, v1);
            *(uint32_t*)(pCl + (size_t)r0 * Nd + col) =
                pack2h(v0 - hfround(v0), v1 - hfround(v1));
            *(uint32_t*)(pCh + (size_t)(r0+8) * Nd + col) = pack2h(v2, v3);
            *(uint32_t*)(pCl + (size_t)(r0+8) * Nd + col) =
                pack2h(v2 - hfround(v2), v3 - hfround(v3));
        }
    }
}

// ---------------------------------------------------------------------------
// fp16 2-mma proj GEMM, distance-4 statement interleave.
// ---------------------------------------------------------------------------
#define F_OFF_AH 0
#define F_OFF_AL REGB
#define F_OFF_BH (2*REGB)
#define F_STAGE  (3*REGB)
#define GEMM_SMEM_F16 (2*F_STAGE)

__global__ void __launch_bounds__(256, 2)
gemm_f16x2(const __half* __restrict__ Ah,
           const __half* __restrict__ Al,
           const uint32_t* __restrict__ Bh,
           const float* __restrict__ bias,
           float* __restrict__ C,
           int Ndim, int Kdim)
{
    extern __shared__ char sm[];
    const uint32_t smb = smem_u32(sm);
    const int tid = threadIdx.x;
    const int lane = tid & 31, wid = tid >> 5;
    const int warp_row = wid & 3, warp_col = wid >> 2;
    const int m0 = blockIdx.y << 7, n0 = blockIdx.x << 7;
    const int lr = lane >> 2, lc = lane & 3;
    const int KH = Kdim >> 1;

    float acc[2][8][4];
    #pragma unroll
    for (int mt = 0; mt < 2; mt++)
        #pragma unroll
        for (int nt = 0; nt < 8; nt++)
            #pragma unroll
            for (int i = 0; i < 4; i++) acc[mt][nt][i] = 0.f;

    const int crow = tid >> 2, cch = tid & 3;
    const int nk = Kdim >> 5;

    auto issue = [&](int kc) {
        const uint32_t base = smb + (kc & 1) * F_STAGE;
        const int k0 = kc << 5, kp0 = kc << 4;
        #pragma unroll
        for (int p = 0; p < 2; p++) {
            int row = p * 64 + crow;
            uint32_t d = base + row * SROWB + cch * 16;
            CP16(d + F_OFF_AH, Ah + (size_t)(m0 + row) * Kdim + k0 + cch * 8);
            CP16(d + F_OFF_AL, Al + (size_t)(m0 + row) * Kdim + k0 + cch * 8);
            CP16(d + F_OFF_BH, Bh + (size_t)(n0 + row) * KH + kp0 + cch * 4);
        }
        CP_COMMIT();
    };

    issue(0);
    if (nk > 1) issue(1);

    const int a_row = lane & 15, a_koff = lane & 16;
    const int b_row = (lane & 7) + ((lane & 16) ? 8 : 0);
    const int b_koff = (lane & 8) ? 16 : 0;

    for (int kc = 0; kc < nk; kc++) {
        if (kc + 1 < nk) CP_WAIT(1); else CP_WAIT(0);
        __syncthreads();
        const uint32_t base = smb + (kc & 1) * F_STAGE;

        #pragma unroll
        for (int ks = 0; ks < 2; ks++) {
            uint32_t ah[2][4], al[2][4];
            #pragma unroll
            for (int mt = 0; mt < 2; mt++) {
                uint32_t aa = base + F_OFF_AH
                            + (warp_row*32 + mt*16 + a_row) * SROWB
                            + ks*32 + a_koff;
                LDSM4(ah[mt], aa);
                LDSM4(al[mt], aa + (F_OFF_AL - F_OFF_AH));
            }
            #pragma unroll
            for (int np = 0; np < 4; np++) {
                uint32_t ba = base + F_OFF_BH
                            + (warp_col*64 + np*16 + b_row) * SROWB
                            + ks*32 + b_koff;
                uint32_t bh4[4];
                LDSM4(bh4, ba);
                MMA_F16(acc[0][2*np  ], ah[0], bh4[0], bh4[1]);
                MMA_F16(acc[1][2*np  ], ah[1], bh4[0], bh4[1]);
                MMA_F16(acc[0][2*np+1], ah[0], bh4[2], bh4[3]);
                MMA_F16(acc[1][2*np+1], ah[1], bh4[2], bh4[3]);
                MMA_F16(acc[0][2*np  ], al[0], bh4[0], bh4[1]);
                MMA_F16(acc[1][2*np  ], al[1], bh4[0], bh4[1]);
                MMA_F16(acc[0][2*np+1], al[0], bh4[2], bh4[3]);
                MMA_F16(acc[1][2*np+1], al[1], bh4[2], bh4[3]);
            }
        }
        __syncthreads();
        if (kc + 2 < nk) issue(kc + 2);
    }

    #pragma unroll
    for (int mt = 0; mt < 2; mt++) {
        const int r0 = m0 + warp_row*32 + mt*16 + lr;
        #pragma unroll
        for (int nt = 0; nt < 8; nt++) {
            const int col = n0 + warp_col*64 + nt*8 + lc*2;
            const float2 bv = *(const float2*)(bias + col);
            *(float2*)(C + (size_t)r0 * Ndim + col) =
                make_float2(acc[mt][nt][0] + bv.x, acc[mt][nt][1] + bv.y);
            *(float2*)(C + (size_t)(r0+8) * Ndim + col) =
                make_float2(acc[mt][nt][2] + bv.x, acc[mt][nt][3] + bv.y);
        }
    }
}

// ---------------------------------------------------------------------------
// Attention: exact R10 structure (s-tile 64, persistent Q frags, 1 CTA/SM);
// only change: mma statements interleaved across the 2 sub-targets (dist 2).
// ---------------------------------------------------------------------------
#define KROWB 272
#define STG_L (64*KROWB)
#define STAGE_A (2*64*KROWB)
#define Q_OFF (2*STAGE_A)
#define ATTN_SMEM (2*STAGE_A + 128*KROWB)

__global__ void __launch_bounds__(256, 1)
attn_kernel(const __half* __restrict__ qh,
            const __half* __restrict__ ql,
            const __half* __restrict__ kh,
            const __half* __restrict__ kl,
            __half* __restrict__ yh,
            __half* __restrict__ yl)
{
    extern __shared__ char sm[];
    const uint32_t smb = smem_u32(sm);
    const int tid = threadIdx.x;
    const int lane = tid & 31, w = tid >> 5;
    const int lr = lane >> 2, lc = lane & 3;
    const int qt = (int)gridDim.x - 1 - (int)blockIdx.x;   // heavy first
    const int bhid = blockIdx.y;
    const int b = bhid >> 4, h = bhid & 15;

    const char* qbh = (const char*)(qh + ((size_t)b*TSEQ + qt*128)*QSTR + h*LDIM);
    const char* qbl = (const char*)(ql + ((size_t)b*TSEQ + qt*128)*QSTR + h*LDIM);
    const char* kbh = (const char*)(kh + (size_t)b*TSEQ*LDIM);
    const char* kbl = (const char*)(kl + (size_t)b*TSEQ*LDIM);

    uint32_t qfh[8][4], qfl[8][4];
    {
        const int qrow = tid >> 4, qch = tid & 15;
        #pragma unroll
        for (int p = 0; p < 8; p++) {
            int row = p*16 + qrow;
            CP16(smb + Q_OFF + row*KROWB + qch*16, qbh + (size_t)row*QSTR*2 + qch*16);
        }
        CP_COMMIT(); CP_WAIT(0); __syncthreads();
        #pragma unroll
        for (int ks = 0; ks < 8; ks++) {
            uint32_t a = smb + Q_OFF + (w*16 + (lane & 15))*KROWB + ks*32 + (lane & 16);
            LDSM4(qfh[ks], a);
        }
        __syncthreads();
        #pragma unroll
        for (int p = 0; p < 8; p++) {
            int row = p*16 + qrow;
            CP16(smb + Q_OFF + row*KROWB + qch*16, qbl + (size_t)row*QSTR*2 + qch*16);
        }
        CP_COMMIT(); CP_WAIT(0); __syncthreads();
        #pragma unroll
        for (int ks = 0; ks < 8; ks++) {
            uint32_t a = smb + Q_OFF + (w*16 + (lane & 15))*KROWB + ks*32 + (lane & 16);
            LDSM4(qfl[ks], a);
        }
        __syncthreads();
    }

    float yacc[16][4];
    #pragma unroll
    for (int nt = 0; nt < 16; nt++)
        #pragma unroll
        for (int i = 0; i < 4; i++) yacc[nt][i] = 0.f;
    float m0 = -1e30f, m1 = -1e30f, l0 = 0.f, l1 = 0.f;

    const int nkt = 2*qt + 2;
    const int krow = tid >> 4, kch = tid & 15;

    auto issueK = [&](int kt) {
        const uint32_t base = smb + (kt & 1) * STAGE_A;
        #pragma unroll
        for (int p = 0; p < 4; p++) {
            int row = p*16 + krow;
            uint32_t d = base + row*KROWB + kch*16;
            CP16(d,         kbh + (size_t)(kt*64 + row)*256 + kch*16);
            CP16(d + STG_L, kbl + (size_t)(kt*64 + row)*256 + kch*16);
        }
        CP_COMMIT();
    };

    issueK(0);
    if (nkt > 1) issueK(1);

    const float scale = 0.08838834764831845f;
    const int t0g = qt*128 + w*16 + lr, t1g = t0g + 8;
    const int wmax = qt*128 + w*16 + 15;

    for (int kt = 0; kt < nkt; kt++) {
        if (kt + 1 < nkt) CP_WAIT(1); else CP_WAIT(0);
        __syncthreads();
        const uint32_t base = smb + (kt & 1) * STAGE_A;
        const bool diagband = (kt >= 2*qt);
        const bool wskip = diagband && (kt*64 > wmax);

        if (!wskip) {
            float sacc[8][4];
            #pragma unroll
            for (int nt = 0; nt < 8; nt++)
                #pragma unroll
                for (int i = 0; i < 4; i++) sacc[nt][i] = 0.f;

            const int sb_row = (lane & 7) + ((lane & 16) ? 8 : 0);
            const int sb_koff = (lane & 8) ? 16 : 0;
            #pragma unroll
            for (int np = 0; np < 4; np++) {
                if (diagband && kt*64 + np*16 > wmax) break;
                #pragma unroll
                for (int ks = 0; ks < 8; ks++) {
                    uint32_t ba = base + (np*16 + sb_row)*KROWB + ks*32 + sb_koff;
                    uint32_t bh4[4], bl4[4];
                    LDSM4(bh4, ba);
                    LDSM4(bl4, ba + STG_L);
                    // distance-2 interleave across the 2 sub-targets
                    MMA_F16(sacc[2*np  ], qfh[ks], bh4[0], bh4[1]);
                    MMA_F16(sacc[2*np+1], qfh[ks], bh4[2], bh4[3]);
                    MMA_F16(sacc[2*np  ], qfl[ks], bh4[0], bh4[1]);
                    MMA_F16(sacc[2*np+1], qfl[ks], bh4[2], bh4[3]);
                    MMA_F16(sacc[2*np  ], qfh[ks], bl4[0], bl4[1]);
                    MMA_F16(sacc[2*np+1], qfh[ks], bl4[2], bl4[3]);
                }
            }

            #pragma unroll
            for (int nt = 0; nt < 8; nt++)
                #pragma unroll
                for (int i = 0; i < 4; i++) sacc[nt][i] *= scale;
            if (diagband) {
                #pragma unroll
                for (int nt = 0; nt < 8; nt++) {
                    int s0 = kt*64 + nt*8 + 2*lc;
                    if (s0     > t0g) sacc[nt][0] = -1e30f;
                    if (s0 + 1 > t0g) sacc[nt][1] = -1e30f;
                    if (s0     > t1g) sacc[nt][2] = -1e30f;
                    if (s0 + 1 > t1g) sacc[nt][3] = -1e30f;
                }
            }

            float mx0 = -1e30f, mx1 = -1e30f;
            #pragma unroll
            for (int nt = 0; nt < 8; nt++) {
                mx0 = fmaxf(mx0, fmaxf(sacc[nt][0], sacc[nt][1]));
                mx1 = fmaxf(mx1, fmaxf(sacc[nt][2], sacc[nt][3]));
            }
            mx0 = fmaxf(mx0, __shfl_xor_sync(0xffffffffu, mx0, 1));
            mx0 = fmaxf(mx0, __shfl_xor_sync(0xffffffffu, mx0, 2));
            mx1 = fmaxf(mx1, __shfl_xor_sync(0xffffffffu, mx1, 1));
            mx1 = fmaxf(mx1, __shfl_xor_sync(0xffffffffu, mx1, 2));
            float m0n = fmaxf(m0, mx0), m1n = fmaxf(m1, mx1);
            float c0 = __expf(m0 - m0n), c1 = __expf(m1 - m1n);
            float s0sum = 0.f, s1sum = 0.f;
            #pragma unroll
            for (int nt = 0; nt < 8; nt++) {
                float p0 = __expf(sacc[nt][0] - m0n);
                float p1 = __expf(sacc[nt][1] - m0n);
                float p2 = __expf(sacc[nt][2] - m1n);
                float p3 = __expf(sacc[nt][3] - m1n);
                s0sum += p0 + p1; s1sum += p2 + p3;
                sacc[nt][0] = p0; sacc[nt][1] = p1;
                sacc[nt][2] = p2; sacc[nt][3] = p3;
            }
            s0sum += __shfl_xor_sync(0xffffffffu, s0sum, 1);
            s0sum += __shfl_xor_sync(0xffffffffu, s0sum, 2);
            s1sum += __shfl_xor_sync(0xffffffffu, s1sum, 1);
            s1sum += __shfl_xor_sync(0xffffffffu, s1sum, 2);
            l0 = l0*c0 + s0sum; l1 = l1*c1 + s1sum;
            m0 = m0n; m1 = m1n;
            #pragma unroll
            for (int nt = 0; nt < 16; nt++) {
                yacc[nt][0] *= c0; yacc[nt][1] *= c0;
                yacc[nt][2] *= c1; yacc[nt][3] *= c1;
            }

            uint32_t pah[4][4], pal[4][4];
            #pragma unroll
            for (int ks2 = 0; ks2 < 4; ks2++) {
                float p0 = sacc[2*ks2][0], p1 = sacc[2*ks2][1];
                float p2 = sacc[2*ks2][2], p3 = sacc[2*ks2][3];
                float q0 = sacc[2*ks2+1][0], q1 = sacc[2*ks2+1][1];
                float q2 = sacc[2*ks2+1][2], q3 = sacc[2*ks2+1][3];
                pah[ks2][0] = pack2h(p0, p1); pah[ks2][1] = pack2h(p2, p3);
                pah[ks2][2] = pack2h(q0, q1); pah[ks2][3] = pack2h(q2, q3);
                pal[ks2][0] = pack2h(p0 - hfround(p0), p1 - hfround(p1));
                pal[ks2][1] = pack2h(p2 - hfround(p2), p3 - hfround(p3));
                pal[ks2][2] = pack2h(q0 - hfround(q0), q1 - hfround(q1));
                pal[ks2][3] = pack2h(q2 - hfround(q2), q3 - hfround(q3));
            }

            #pragma unroll
            for (int ks2 = 0; ks2 < 4; ks2++) {
                if (diagband && kt*64 + ks2*16 > wmax) break;
                #pragma unroll
                for (int np = 0; np < 8; np++) {
                    uint32_t va = base + (ks2*16 + (lane & 15))*KROWB
                                + np*32 + (lane & 16);
                    uint32_t vh4[4];
                    LDSM4T(vh4, va);
                    // distance-2 interleave across the 2 sub-targets
                    MMA_F16(yacc[2*np  ], pah[ks2], vh4[0], vh4[1]);
                    MMA_F16(yacc[2*np+1], pah[ks2], vh4[2], vh4[3]);
                    MMA_F16(yacc[2*np  ], pal[ks2], vh4[0], vh4[1]);
                    MMA_F16(yacc[2*np+1], pal[ks2], vh4[2], vh4[3]);
                }
            }
        }
        __syncthreads();
        if (kt + 2 < nkt) issueK(kt + 2);
    }

    const float li0 = 1.0f / l0, li1 = 1.0f / l1;
    #pragma unroll
    for (int nt = 0; nt < 16; nt++) {
        float v0 = yacc[nt][0]*li0, v1 = yacc[nt][1]*li0;
        float v2 = yacc[nt][2]*li1, v3 = yacc[nt][3]*li1;
        size_t o0 = ((size_t)b*TSEQ + t0g)*QSTR + h*LDIM + nt*8 + 2*lc;
        size_t o1 = o0 + (size_t)8*QSTR;
        *(uint32_t*)(yh + o0) = pack2h(v0, v1);
        *(uint32_t*)(yl + o0) = pack2h(v0 - hfround(v0), v1 - hfround(v1));
        *(uint32_t*)(yh + o1) = pack2h(v2, v3);
        *(uint32_t*)(yl + o1) = pack2h(v2 - hfround(v2), v3 - hfround(v3));
    }
}

// ---------------------------------------------------------------------------
extern "C" void kernel_launch(void* const* d_in, const int* in_sizes, int n_in,
                              void* d_out, int out_size)
{
    const float* x      = (const float*)d_in[0];
    const float* W_lat  = (const float*)d_in[1];
    const float* b_lat  = (const float*)d_in[2];
    const float* W_d    = (const float*)d_in[3];
    const float* b_d    = (const float*)d_in[4];
    const float* W_proj = (const float*)d_in[5];
    const float* b_proj = (const float*)d_in[6];
    float* out = (float*)d_out;

    __half *xh, *xl, *qhp, *qlp, *khp, *klp, *yhp, *ylp;
    uint32_t *wdh, *wph, *wlh, *wll;
    cudaGetSymbolAddress((void**)&xh,  g_xh);
    cudaGetSymbolAddress((void**)&xl,  g_xl);
    cudaGetSymbolAddress((void**)&qhp, g_qh);
    cudaGetSymbolAddress((void**)&qlp, g_ql);
    cudaGetSymbolAddress((void**)&khp, g_kh);
    cudaGetSymbolAddress((void**)&klp, g_kl);
    cudaGetSymbolAddress((void**)&yhp, g_yh);
    cudaGetSymbolAddress((void**)&ylp, g_yl);
    cudaGetSymbolAddress((void**)&wdh, g_wdh);
    cudaGetSymbolAddress((void**)&wph, g_wph);
    cudaGetSymbolAddress((void**)&wlh, g_wlh);
    cudaGetSymbolAddress((void**)&wll, g_wll);

    cudaFuncSetAttribute((const void*)gemm_f16qk,
                         cudaFuncAttributeMaxDynamicSharedMemorySize, GEMM_SMEM);
    cudaFuncSetAttribute((const void*)gemm_f16x2,
                         cudaFuncAttributeMaxDynamicSharedMemorySize, GEMM_SMEM_F16);
    cudaFuncSetAttribute((const void*)attn_kernel,
                         cudaFuncAttributeMaxDynamicSharedMemorySize, ATTN_SMEM);

    dim3 tb(32, 8);
    // 0) split x -> fp16 hi/lo
    split_rows<<<(MROWS*CEMB/4 + 255)/256, 256>>>(x, xh, xl, MROWS*CEMB);
    // 1) combined pack: W_d (hi) + W_lat (hi/lo)
    pack_wd_wlat<<<dim3(CEMB/32, 64 + LDIM/32), tb>>>(W_d, wdh, W_lat, wlh, wll);
    // 2) fused q (2-term) + k (3-term) GEMM
    gemm_f16qk<<<dim3(QSTR/128 + 1, MROWS/128), 256, GEMM_SMEM>>>(
        xh, xl, wdh, b_d, qhp, qlp, QSTR, CEMB,
        wlh, wll, b_lat, khp, klp, LDIM);
    // 3) attention                                   <-- ncu-profiled slot
    attn_kernel<<<dim3(TSEQ/128, BATCH*NHEAD), 256, ATTN_SMEM>>>(
        qhp, qlp, khp, klp, yhp, ylp);
    // 4) pack W_proj (fp16 hi only)
    split_pack_h<<<dim3(QSTR/32, CEMB/32), tb>>>(W_proj, wph, QSTR, CEMB);
    // 5) out = y @ W_proj + b_proj
    gemm_f16x2<<<dim3(CEMB/128, MROWS/128), 256, GEMM_SMEM_F16>>>(
        yhp, ylp, wph, b_proj, out, CEMB, CEMB);
}

// round 17
// speedup vs baseline: 1.7463x; 1.1330x over previous
#include <cuda_runtime.h>
#include <cuda_fp16.h>
#include <cstdint>

#define BATCH 2
#define TSEQ 2048
#define CEMB 2048
#define NHEAD 16
#define LDIM 128
#define MROWS (BATCH*TSEQ)
#define QSTR (NHEAD*LDIM)   // 2048

// ---------------------------------------------------------------------------
// Scratch (__device__ globals: allocation-free rule). All fp16.
// ---------------------------------------------------------------------------
__device__ __half g_xh[MROWS*CEMB], g_xl[MROWS*CEMB];   // x split
__device__ __half g_qh[MROWS*QSTR], g_ql[MROWS*QSTR];   // q split
__device__ __half g_kh[MROWS*LDIM], g_kl[MROWS*LDIM];   // k split
__device__ __half g_yh[MROWS*QSTR];                     // y (fp16 hi only)
__device__ uint32_t g_wdh[QSTR*(CEMB/2)];               // W_d    fp16 HI pairs
__device__ uint32_t g_wlh[LDIM*(CEMB/2)], g_wll[LDIM*(CEMB/2)];  // W_lat hi/lo
__device__ uint32_t g_wph[CEMB*(QSTR/2)];               // W_proj fp16 HI pairs

// ---------------------------------------------------------------------------
// Helpers
// ---------------------------------------------------------------------------
__device__ __forceinline__ uint32_t smem_u32(const void* p){
    uint32_t a;
    asm("{ .reg .u64 t; cvta.to.shared.u64 t, %1; cvt.u32.u64 %0, t; }"
        : "=r"(a) : "l"(p));
    return a;
}
__device__ __forceinline__ float hfround(float x){
    return __half2float(__float2half_rn(x));
}
__device__ __forceinline__ uint32_t pack2h(float lo, float hi){
    uint32_t r;
    asm("cvt.rn.f16x2.f32 %0, %1, %2;" : "=r"(r) : "f"(hi), "f"(lo));
    return r;
}

#define CP16(dst_u32, src_ptr) \
    asm volatile("cp.async.cg.shared.global [%0], [%1], 16;" \
                 :: "r"(dst_u32), "l"(src_ptr) : "memory")
#define CP_COMMIT() asm volatile("cp.async.commit_group;" ::: "memory")
#define CP_WAIT(n)  asm volatile("cp.async.wait_group %0;" :: "n"(n) : "memory")

#define LDSM4(R, ADDR)                                                        \
    asm volatile("ldmatrix.sync.aligned.m8n8.x4.shared.b16 {%0,%1,%2,%3}, [%4];" \
        : "=r"((R)[0]), "=r"((R)[1]), "=r"((R)[2]), "=r"((R)[3]) : "r"(ADDR))
#define LDSM4T(R, ADDR)                                                       \
    asm volatile("ldmatrix.sync.aligned.m8n8.x4.trans.shared.b16 {%0,%1,%2,%3}, [%4];" \
        : "=r"((R)[0]), "=r"((R)[1]), "=r"((R)[2]), "=r"((R)[3]) : "r"(ADDR))

// volatile is load-bearing: keeps ptxas from stretching live ranges (R14 blew
// regs 128->231 in the GEMMs without it). Order freedom = statement order.
#define MMA_F16(acc, a, b0, b1)                                               \
    asm volatile(                                                             \
        "mma.sync.aligned.m16n8k16.row.col.f32.f16.f16.f32 "                  \
        "{%0,%1,%2,%3}, {%4,%5,%6,%7}, {%8,%9}, {%0,%1,%2,%3};"               \
        : "+f"((acc)[0]), "+f"((acc)[1]), "+f"((acc)[2]), "+f"((acc)[3])      \
        : "r"((a)[0]), "r"((a)[1]), "r"((a)[2]), "r"((a)[3]),                 \
          "r"(b0), "r"(b1))

// ---------------------------------------------------------------------------
// Split fp32 -> (hi, lo) fp16
// ---------------------------------------------------------------------------
__global__ void split_rows(const float* __restrict__ src,
                           __half* __restrict__ hi,
                           __half* __restrict__ lo, int n)
{
    int i = (blockIdx.x * 256 + threadIdx.x) * 4;
    if (i >= n) return;
    float4 v = *(const float4*)(src + i);
    *(uint32_t*)(hi + i)     = pack2h(v.x, v.y);
    *(uint32_t*)(hi + i + 2) = pack2h(v.z, v.w);
    *(uint32_t*)(lo + i)     = pack2h(v.x - hfround(v.x), v.y - hfround(v.y));
    *(uint32_t*)(lo + i + 2) = pack2h(v.z - hfround(v.z), v.w - hfround(v.w));
}

// ---------------------------------------------------------------------------
// Combined weight pack: by<64 -> W_d (hi only); by>=64 -> W_lat (hi/lo).
// ---------------------------------------------------------------------------
__global__ void pack_wd_wlat(const float* __restrict__ Wd,
                             uint32_t* __restrict__ wdh,
                             const float* __restrict__ Wlat,
                             uint32_t* __restrict__ wlh,
                             uint32_t* __restrict__ wll)
{
    __shared__ float t[32][33];
    const int k0 = blockIdx.x * 32;
    const int tx = threadIdx.x, ty = threadIdx.y;
    const bool lat = (blockIdx.y >= 64);
    const int n0 = lat ? (blockIdx.y - 64) * 32 : blockIdx.y * 32;
    const float* W = lat ? Wlat : Wd;
    const int N = lat ? LDIM : QSTR;
    for (int i = ty; i < 32; i += 8)
        t[i][tx] = W[(size_t)(k0 + i) * N + n0 + tx];
    __syncthreads();
    if (tx < 16) {
        for (int i = ty; i < 32; i += 8) {
            float v0 = t[2*tx][i], v1 = t[2*tx+1][i];
            size_t o = (size_t)(n0 + i) * (CEMB >> 1) + (k0 >> 1) + tx;
            if (lat) {
                wlh[o] = pack2h(v0, v1);
                wll[o] = pack2h(v0 - hfround(v0), v1 - hfround(v1));
            } else {
                wdh[o] = pack2h(v0, v1);
            }
        }
    }
}

// ---------------------------------------------------------------------------
// Transpose-pack fp16 HI only (W_proj)
// ---------------------------------------------------------------------------
__global__ void split_pack_h(const float* __restrict__ W,
                             uint32_t* __restrict__ hp, int K, int N)
{
    __shared__ float t[32][33];
    const int k0 = blockIdx.x * 32, n0 = blockIdx.y * 32;
    const int tx = threadIdx.x, ty = threadIdx.y;
    for (int i = ty; i < 32; i += 8)
        t[i][tx] = W[(size_t)(k0 + i) * N + n0 + tx];
    __syncthreads();
    if (tx < 16) {
        for (int i = ty; i < 32; i += 8) {
            float v0 = t[2*tx][i], v1 = t[2*tx+1][i];
            hp[(size_t)(n0 + i) * (K >> 1) + (k0 >> 1) + tx] = pack2h(v0, v1);
        }
    }
}

// ---------------------------------------------------------------------------
// Fused q/k GEMM (fp16): q 2-term, latent column 3-term. (unchanged R16)
// ---------------------------------------------------------------------------
#define SROWB 80
#define REGB  (128*SROWB)
#define OFF_AH 0
#define OFF_AL REGB
#define OFF_BH (2*REGB)
#define OFF_BL (3*REGB)
#define STAGE  (4*REGB)
#define GEMM_SMEM (2*STAGE)

__global__ void __launch_bounds__(256, 2)
gemm_f16qk(const __half* __restrict__ Ah,
           const __half* __restrict__ Al,
           const uint32_t* __restrict__ Bh,
           const float* __restrict__ bias,
           __half* __restrict__ Ch,
           __half* __restrict__ Cl,
           int Ndim, int Kdim,
           const uint32_t* __restrict__ B2h,
           const uint32_t* __restrict__ B2l,
           const float* __restrict__ bias2,
           __half* __restrict__ C2h,
           __half* __restrict__ C2l,
           int N2)
{
    extern __shared__ char sm[];
    const uint32_t smb = smem_u32(sm);
    const int tid = threadIdx.x;
    const int lane = tid & 31, wid = tid >> 5;
    const int warp_row = wid & 3, warp_col = wid >> 2;
    const int m0 = blockIdx.y << 7;
    const int lr = lane >> 2, lc = lane & 3;
    const int KH = Kdim >> 1;

    const uint32_t* pBh = Bh;  const uint32_t* pBl = nullptr;
    const float* pbias = bias;
    __half* pCh = Ch;          __half* pCl = Cl;
    int Nd = Ndim;
    int n0 = blockIdx.x << 7;
    const bool lat3 = (n0 >= Ndim);
    if (lat3) {
        pBh = B2h; pBl = B2l; pbias = bias2; pCh = C2h; pCl = C2l;
        Nd = N2; n0 = 0;
    }

    float acc[2][8][4];
    #pragma unroll
    for (int mt = 0; mt < 2; mt++)
        #pragma unroll
        for (int nt = 0; nt < 8; nt++)
            #pragma unroll
            for (int i = 0; i < 4; i++) acc[mt][nt][i] = 0.f;

    const int crow = tid >> 2, cch = tid & 3;
    const int nk = Kdim >> 5;

    auto issue = [&](int kc) {
        const uint32_t base = smb + (kc & 1) * STAGE;
        const int k0 = kc << 5, kp0 = kc << 4;
        #pragma unroll
        for (int p = 0; p < 2; p++) {
            int row = p * 64 + crow;
            uint32_t d = base + row * SROWB + cch * 16;
            CP16(d + OFF_AH, Ah + (size_t)(m0 + row) * Kdim + k0 + cch * 8);
            CP16(d + OFF_AL, Al + (size_t)(m0 + row) * Kdim + k0 + cch * 8);
            CP16(d + OFF_BH, pBh + (size_t)(n0 + row) * KH + kp0 + cch * 4);
            if (lat3)
                CP16(d + OFF_BL, pBl + (size_t)(n0 + row) * KH + kp0 + cch * 4);
        }
        CP_COMMIT();
    };

    issue(0);
    if (nk > 1) issue(1);

    const int a_row = lane & 15, a_koff = lane & 16;
    const int b_row = (lane & 7) + ((lane & 16) ? 8 : 0);
    const int b_koff = (lane & 8) ? 16 : 0;

    for (int kc = 0; kc < nk; kc++) {
        if (kc + 1 < nk) CP_WAIT(1); else CP_WAIT(0);
        __syncthreads();
        const uint32_t base = smb + (kc & 1) * STAGE;

        #pragma unroll
        for (int ks = 0; ks < 2; ks++) {
            uint32_t ah[2][4], al[2][4];
            #pragma unroll
            for (int mt = 0; mt < 2; mt++) {
                uint32_t aa = base + OFF_AH
                            + (warp_row*32 + mt*16 + a_row) * SROWB
                            + ks*32 + a_koff;
                LDSM4(ah[mt], aa);
                LDSM4(al[mt], aa + (OFF_AL - OFF_AH));
            }
            #pragma unroll
            for (int np = 0; np < 4; np++) {
                uint32_t ba = base + OFF_BH
                            + (warp_col*64 + np*16 + b_row) * SROWB
                            + ks*32 + b_koff;
                uint32_t bh4[4], bl4[4];
                LDSM4(bh4, ba);
                if (lat3) LDSM4(bl4, ba + (OFF_BL - OFF_BH));
                MMA_F16(acc[0][2*np  ], ah[0], bh4[0], bh4[1]);
                MMA_F16(acc[1][2*np  ], ah[1], bh4[0], bh4[1]);
                MMA_F16(acc[0][2*np+1], ah[0], bh4[2], bh4[3]);
                MMA_F16(acc[1][2*np+1], ah[1], bh4[2], bh4[3]);
                MMA_F16(acc[0][2*np  ], al[0], bh4[0], bh4[1]);
                MMA_F16(acc[1][2*np  ], al[1], bh4[0], bh4[1]);
                MMA_F16(acc[0][2*np+1], al[0], bh4[2], bh4[3]);
                MMA_F16(acc[1][2*np+1], al[1], bh4[2], bh4[3]);
                if (lat3) {
                    MMA_F16(acc[0][2*np  ], ah[0], bl4[0], bl4[1]);
                    MMA_F16(acc[1][2*np  ], ah[1], bl4[0], bl4[1]);
                    MMA_F16(acc[0][2*np+1], ah[0], bl4[2], bl4[3]);
                    MMA_F16(acc[1][2*np+1], ah[1], bl4[2], bl4[3]);
                }
            }
        }
        __syncthreads();
        if (kc + 2 < nk) issue(kc + 2);
    }

    #pragma unroll
    for (int mt = 0; mt < 2; mt++) {
        const int r0 = m0 + warp_row*32 + mt*16 + lr;
        #pragma unroll
        for (int nt = 0; nt < 8; nt++) {
            const int col = n0 + warp_col*64 + nt*8 + lc*2;
            const float2 bv = *(const float2*)(pbias + col);
            float v0 = acc[mt][nt][0] + bv.x, v1 = acc[mt][nt][1] + bv.y;
            float v2 = acc[mt][nt][2] + bv.x, v3 = acc[mt][nt][3] + bv.y;
            *(uint32_t*)(pCh + (size_t)r0 * Nd + col) = pack2h(v0, v1);
            *(uint32_t*)(pCl + (size_t)r0 * Nd + col) =
                pack2h(v0 - hfround(v0), v1 - hfround(v1));
            *(uint32_t*)(pCh + (size_t)(r0+8) * Nd + col) = pack2h(v2, v3);
            *(uint32_t*)(pCl + (size_t)(r0+8) * Nd + col) =
                pack2h(v2 - hfround(v2), v3 - hfround(v3));
        }
    }
}

// ---------------------------------------------------------------------------
// fp16 SINGLE-term proj GEMM:  out = y_hi @ Wp_hi + bias  (error linear in out)
// 32 mma / kc, 12 LDSM, 20KB stage.
// ---------------------------------------------------------------------------
#define P_OFF_AH 0
#define P_OFF_BH REGB
#define P_STAGE  (2*REGB)                 // 20480
#define GEMM_SMEM_P (2*P_STAGE)           // 40960

__global__ void __launch_bounds__(256, 2)
gemm_f16x1(const __half* __restrict__ Ah,
           const uint32_t* __restrict__ Bh,
           const float* __restrict__ bias,
           float* __restrict__ C,
           int Ndim, int Kdim)
{
    extern __shared__ char sm[];
    const uint32_t smb = smem_u32(sm);
    const int tid = threadIdx.x;
    const int lane = tid & 31, wid = tid >> 5;
    const int warp_row = wid & 3, warp_col = wid >> 2;
    const int m0 = blockIdx.y << 7, n0 = blockIdx.x << 7;
    const int lr = lane >> 2, lc = lane & 3;
    const int KH = Kdim >> 1;

    float acc[2][8][4];
    #pragma unroll
    for (int mt = 0; mt < 2; mt++)
        #pragma unroll
        for (int nt = 0; nt < 8; nt++)
            #pragma unroll
            for (int i = 0; i < 4; i++) acc[mt][nt][i] = 0.f;

    const int crow = tid >> 2, cch = tid & 3;
    const int nk = Kdim >> 5;

    auto issue = [&](int kc) {
        const uint32_t base = smb + (kc & 1) * P_STAGE;
        const int k0 = kc << 5, kp0 = kc << 4;
        #pragma unroll
        for (int p = 0; p < 2; p++) {
            int row = p * 64 + crow;
            uint32_t d = base + row * SROWB + cch * 16;
            CP16(d + P_OFF_AH, Ah + (size_t)(m0 + row) * Kdim + k0 + cch * 8);
            CP16(d + P_OFF_BH, Bh + (size_t)(n0 + row) * KH + kp0 + cch * 4);
        }
        CP_COMMIT();
    };

    issue(0);
    if (nk > 1) issue(1);

    const int a_row = lane & 15, a_koff = lane & 16;
    const int b_row = (lane & 7) + ((lane & 16) ? 8 : 0);
    const int b_koff = (lane & 8) ? 16 : 0;

    for (int kc = 0; kc < nk; kc++) {
        if (kc + 1 < nk) CP_WAIT(1); else CP_WAIT(0);
        __syncthreads();
        const uint32_t base = smb + (kc & 1) * P_STAGE;

        #pragma unroll
        for (int ks = 0; ks < 2; ks++) {
            uint32_t ah[2][4];
            #pragma unroll
            for (int mt = 0; mt < 2; mt++) {
                uint32_t aa = base + P_OFF_AH
                            + (warp_row*32 + mt*16 + a_row) * SROWB
                            + ks*32 + a_koff;
                LDSM4(ah[mt], aa);
            }
            #pragma unroll
            for (int np = 0; np < 4; np++) {
                uint32_t ba = base + P_OFF_BH
                            + (warp_col*64 + np*16 + b_row) * SROWB
                            + ks*32 + b_koff;
                uint32_t bh4[4];
                LDSM4(bh4, ba);
                MMA_F16(acc[0][2*np  ], ah[0], bh4[0], bh4[1]);
                MMA_F16(acc[1][2*np  ], ah[1], bh4[0], bh4[1]);
                MMA_F16(acc[0][2*np+1], ah[0], bh4[2], bh4[3]);
                MMA_F16(acc[1][2*np+1], ah[1], bh4[2], bh4[3]);
            }
        }
        __syncthreads();
        if (kc + 2 < nk) issue(kc + 2);
    }

    #pragma unroll
    for (int mt = 0; mt < 2; mt++) {
        const int r0 = m0 + warp_row*32 + mt*16 + lr;
        #pragma unroll
        for (int nt = 0; nt < 8; nt++) {
            const int col = n0 + warp_col*64 + nt*8 + lc*2;
            const float2 bv = *(const float2*)(bias + col);
            *(float2*)(C + (size_t)r0 * Ndim + col) =
                make_float2(acc[mt][nt][0] + bv.x, acc[mt][nt][1] + bv.y);
            *(float2*)(C + (size_t)(r0+8) * Ndim + col) =
                make_float2(acc[mt][nt][2] + bv.x, acc[mt][nt][3] + bv.y);
        }
    }
}

// ---------------------------------------------------------------------------
// Attention: R16 structure; epilogue writes y-hi only; l-reduction deferred
// to epilogue (c-factors are quad-uniform, so lane-partial l is exact).
// ---------------------------------------------------------------------------
#define KROWB 272
#define STG_L (64*KROWB)
#define STAGE_A (2*64*KROWB)
#define Q_OFF (2*STAGE_A)
#define ATTN_SMEM (2*STAGE_A + 128*KROWB)

__global__ void __launch_bounds__(256, 1)
attn_kernel(const __half* __restrict__ qh,
            const __half* __restrict__ ql,
            const __half* __restrict__ kh,
            const __half* __restrict__ kl,
            __half* __restrict__ yh)
{
    extern __shared__ char sm[];
    const uint32_t smb = smem_u32(sm);
    const int tid = threadIdx.x;
    const int lane = tid & 31, w = tid >> 5;
    const int lr = lane >> 2, lc = lane & 3;
    const int qt = (int)gridDim.x - 1 - (int)blockIdx.x;   // heavy first
    const int bhid = blockIdx.y;
    const int b = bhid >> 4, h = bhid & 15;

    const char* qbh = (const char*)(qh + ((size_t)b*TSEQ + qt*128)*QSTR + h*LDIM);
    const char* qbl = (const char*)(ql + ((size_t)b*TSEQ + qt*128)*QSTR + h*LDIM);
    const char* kbh = (const char*)(kh + (size_t)b*TSEQ*LDIM);
    const char* kbl = (const char*)(kl + (size_t)b*TSEQ*LDIM);

    uint32_t qfh[8][4], qfl[8][4];
    {
        const int qrow = tid >> 4, qch = tid & 15;
        #pragma unroll
        for (int p = 0; p < 8; p++) {
            int row = p*16 + qrow;
            CP16(smb + Q_OFF + row*KROWB + qch*16, qbh + (size_t)row*QSTR*2 + qch*16);
        }
        CP_COMMIT(); CP_WAIT(0); __syncthreads();
        #pragma unroll
        for (int ks = 0; ks < 8; ks++) {
            uint32_t a = smb + Q_OFF + (w*16 + (lane & 15))*KROWB + ks*32 + (lane & 16);
            LDSM4(qfh[ks], a);
        }
        __syncthreads();
        #pragma unroll
        for (int p = 0; p < 8; p++) {
            int row = p*16 + qrow;
            CP16(smb + Q_OFF + row*KROWB + qch*16, qbl + (size_t)row*QSTR*2 + qch*16);
        }
        CP_COMMIT(); CP_WAIT(0); __syncthreads();
        #pragma unroll
        for (int ks = 0; ks < 8; ks++) {
            uint32_t a = smb + Q_OFF + (w*16 + (lane & 15))*KROWB + ks*32 + (lane & 16);
            LDSM4(qfl[ks], a);
        }
        __syncthreads();
    }

    float yacc[16][4];
    #pragma unroll
    for (int nt = 0; nt < 16; nt++)
        #pragma unroll
        for (int i = 0; i < 4; i++) yacc[nt][i] = 0.f;
    float m0 = -1e30f, m1 = -1e30f, l0 = 0.f, l1 = 0.f;   // l: lane-partial

    const int nkt = 2*qt + 2;
    const int krow = tid >> 4, kch = tid & 15;

    auto issueK = [&](int kt) {
        const uint32_t base = smb + (kt & 1) * STAGE_A;
        #pragma unroll
        for (int p = 0; p < 4; p++) {
            int row = p*16 + krow;
            uint32_t d = base + row*KROWB + kch*16;
            CP16(d,         kbh + (size_t)(kt*64 + row)*256 + kch*16);
            CP16(d + STG_L, kbl + (size_t)(kt*64 + row)*256 + kch*16);
        }
        CP_COMMIT();
    };

    issueK(0);
    if (nkt > 1) issueK(1);

    const float scale = 0.08838834764831845f;
    const int t0g = qt*128 + w*16 + lr, t1g = t0g + 8;
    const int wmax = qt*128 + w*16 + 15;

    for (int kt = 0; kt < nkt; kt++) {
        if (kt + 1 < nkt) CP_WAIT(1); else CP_WAIT(0);
        __syncthreads();
        const uint32_t base = smb + (kt & 1) * STAGE_A;
        const bool diagband = (kt >= 2*qt);
        const bool wskip = diagband && (kt*64 > wmax);

        if (!wskip) {
            float sacc[8][4];
            #pragma unroll
            for (int nt = 0; nt < 8; nt++)
                #pragma unroll
                for (int i = 0; i < 4; i++) sacc[nt][i] = 0.f;

            const int sb_row = (lane & 7) + ((lane & 16) ? 8 : 0);
            const int sb_koff = (lane & 8) ? 16 : 0;
            #pragma unroll
            for (int np = 0; np < 4; np++) {
                if (diagband && kt*64 + np*16 > wmax) break;
                #pragma unroll
                for (int ks = 0; ks < 8; ks++) {
                    uint32_t ba = base + (np*16 + sb_row)*KROWB + ks*32 + sb_koff;
                    uint32_t bh4[4], bl4[4];
                    LDSM4(bh4, ba);
                    LDSM4(bl4, ba + STG_L);
                    MMA_F16(sacc[2*np  ], qfh[ks], bh4[0], bh4[1]);
                    MMA_F16(sacc[2*np+1], qfh[ks], bh4[2], bh4[3]);
                    MMA_F16(sacc[2*np  ], qfl[ks], bh4[0], bh4[1]);
                    MMA_F16(sacc[2*np+1], qfl[ks], bh4[2], bh4[3]);
                    MMA_F16(sacc[2*np  ], qfh[ks], bl4[0], bl4[1]);
                    MMA_F16(sacc[2*np+1], qfh[ks], bl4[2], bl4[3]);
                }
            }

            #pragma unroll
            for (int nt = 0; nt < 8; nt++)
                #pragma unroll
                for (int i = 0; i < 4; i++) sacc[nt][i] *= scale;
            if (diagband) {
                #pragma unroll
                for (int nt = 0; nt < 8; nt++) {
                    int s0 = kt*64 + nt*8 + 2*lc;
                    if (s0     > t0g) sacc[nt][0] = -1e30f;
                    if (s0 + 1 > t0g) sacc[nt][1] = -1e30f;
                    if (s0     > t1g) sacc[nt][2] = -1e30f;
                    if (s0 + 1 > t1g) sacc[nt][3] = -1e30f;
                }
            }

            float mx0 = -1e30f, mx1 = -1e30f;
            #pragma unroll
            for (int nt = 0; nt < 8; nt++) {
                mx0 = fmaxf(mx0, fmaxf(sacc[nt][0], sacc[nt][1]));
                mx1 = fmaxf(mx1, fmaxf(sacc[nt][2], sacc[nt][3]));
            }
            mx0 = fmaxf(mx0, __shfl_xor_sync(0xffffffffu, mx0, 1));
            mx0 = fmaxf(mx0, __shfl_xor_sync(0xffffffffu, mx0, 2));
            mx1 = fmaxf(mx1, __shfl_xor_sync(0xffffffffu, mx1, 1));
            mx1 = fmaxf(mx1, __shfl_xor_sync(0xffffffffu, mx1, 2));
            float m0n = fmaxf(m0, mx0), m1n = fmaxf(m1, mx1);
            float c0 = __expf(m0 - m0n), c1 = __expf(m1 - m1n);
            float s0sum = 0.f, s1sum = 0.f;        // lane-partial (no shuffles)
            #pragma unroll
            for (int nt = 0; nt < 8; nt++) {
                float p0 = __expf(sacc[nt][0] - m0n);
                float p1 = __expf(sacc[nt][1] - m0n);
                float p2 = __expf(sacc[nt][2] - m1n);
                float p3 = __expf(sacc[nt][3] - m1n);
                s0sum += p0 + p1; s1sum += p2 + p3;
                sacc[nt][0] = p0; sacc[nt][1] = p1;
                sacc[nt][2] = p2; sacc[nt][3] = p3;
            }
            l0 = l0*c0 + s0sum; l1 = l1*c1 + s1sum;
            m0 = m0n; m1 = m1n;
            #pragma unroll
            for (int nt = 0; nt < 16; nt++) {
                yacc[nt][0] *= c0; yacc[nt][1] *= c0;
                yacc[nt][2] *= c1; yacc[nt][3] *= c1;
            }

            uint32_t pah[4][4], pal[4][4];
            #pragma unroll
            for (int ks2 = 0; ks2 < 4; ks2++) {
                float p0 = sacc[2*ks2][0], p1 = sacc[2*ks2][1];
                float p2 = sacc[2*ks2][2], p3 = sacc[2*ks2][3];
                float q0 = sacc[2*ks2+1][0], q1 = sacc[2*ks2+1][1];
                float q2 = sacc[2*ks2+1][2], q3 = sacc[2*ks2+1][3];
                pah[ks2][0] = pack2h(p0, p1); pah[ks2][1] = pack2h(p2, p3);
                pah[ks2][2] = pack2h(q0, q1); pah[ks2][3] = pack2h(q2, q3);
                pal[ks2][0] = pack2h(p0 - hfround(p0), p1 - hfround(p1));
                pal[ks2][1] = pack2h(p2 - hfround(p2), p3 - hfround(p3));
                pal[ks2][2] = pack2h(q0 - hfround(q0), q1 - hfround(q1));
                pal[ks2][3] = pack2h(q2 - hfround(q2), q3 - hfround(q3));
            }

            #pragma unroll
            for (int ks2 = 0; ks2 < 4; ks2++) {
                if (diagband && kt*64 + ks2*16 > wmax) break;
                #pragma unroll
                for (int np = 0; np < 8; np++) {
                    uint32_t va = base + (ks2*16 + (lane & 15))*KROWB
                                + np*32 + (lane & 16);
                    uint32_t vh4[4];
                    LDSM4T(vh4, va);
                    MMA_F16(yacc[2*np  ], pah[ks2], vh4[0], vh4[1]);
                    MMA_F16(yacc[2*np+1], pah[ks2], vh4[2], vh4[3]);
                    MMA_F16(yacc[2*np  ], pal[ks2], vh4[0], vh4[1]);
                    MMA_F16(yacc[2*np+1], pal[ks2], vh4[2], vh4[3]);
                }
            }
        }
        __syncthreads();
        if (kt + 2 < nkt) issueK(kt + 2);
    }

    // Deferred l reduction (quad): exact same sums, different add order.
    l0 += __shfl_xor_sync(0xffffffffu, l0, 1);
    l0 += __shfl_xor_sync(0xffffffffu, l0, 2);
    l1 += __shfl_xor_sync(0xffffffffu, l1, 1);
    l1 += __shfl_xor_sync(0xffffffffu, l1, 2);

    const float li0 = 1.0f / l0, li1 = 1.0f / l1;
    #pragma unroll
    for (int nt = 0; nt < 16; nt++) {
        float v0 = yacc[nt][0]*li0, v1 = yacc[nt][1]*li0;
        float v2 = yacc[nt][2]*li1, v3 = yacc[nt][3]*li1;
        size_t o0 = ((size_t)b*TSEQ + t0g)*QSTR + h*LDIM + nt*8 + 2*lc;
        size_t o1 = o0 + (size_t)8*QSTR;
        *(uint32_t*)(yh + o0) = pack2h(v0, v1);
        *(uint32_t*)(yh + o1) = pack2h(v2, v3);
    }
}

// ---------------------------------------------------------------------------
extern "C" void kernel_launch(void* const* d_in, const int* in_sizes, int n_in,
                              void* d_out, int out_size)
{
    const float* x      = (const float*)d_in[0];
    const float* W_lat  = (const float*)d_in[1];
    const float* b_lat  = (const float*)d_in[2];
    const float* W_d    = (const float*)d_in[3];
    const float* b_d    = (const float*)d_in[4];
    const float* W_proj = (const float*)d_in[5];
    const float* b_proj = (const float*)d_in[6];
    float* out = (float*)d_out;

    __half *xh, *xl, *qhp, *qlp, *khp, *klp, *yhp;
    uint32_t *wdh, *wph, *wlh, *wll;
    cudaGetSymbolAddress((void**)&xh,  g_xh);
    cudaGetSymbolAddress((void**)&xl,  g_xl);
    cudaGetSymbolAddress((void**)&qhp, g_qh);
    cudaGetSymbolAddress((void**)&qlp, g_ql);
    cudaGetSymbolAddress((void**)&khp, g_kh);
    cudaGetSymbolAddress((void**)&klp, g_kl);
    cudaGetSymbolAddress((void**)&yhp, g_yh);
    cudaGetSymbolAddress((void**)&wdh, g_wdh);
    cudaGetSymbolAddress((void**)&wph, g_wph);
    cudaGetSymbolAddress((void**)&wlh, g_wlh);
    cudaGetSymbolAddress((void**)&wll, g_wll);

    cudaFuncSetAttribute((const void*)gemm_f16qk,
                         cudaFuncAttributeMaxDynamicSharedMemorySize, GEMM_SMEM);
    cudaFuncSetAttribute((const void*)gemm_f16x1,
                         cudaFuncAttributeMaxDynamicSharedMemorySize, GEMM_SMEM_P);
    cudaFuncSetAttribute((const void*)attn_kernel,
                         cudaFuncAttributeMaxDynamicSharedMemorySize, ATTN_SMEM);

    dim3 tb(32, 8);
    // 0) split x -> fp16 hi/lo
    split_rows<<<(MROWS*CEMB/4 + 255)/256, 256>>>(x, xh, xl, MROWS*CEMB);
    // 1) combined pack: W_d (hi) + W_lat (hi/lo)
    pack_wd_wlat<<<dim3(CEMB/32, 64 + LDIM/32), tb>>>(W_d, wdh, W_lat, wlh, wll);
    // 2) fused q (2-term) + k (3-term) GEMM
    gemm_f16qk<<<dim3(QSTR/128 + 1, MROWS/128), 256, GEMM_SMEM>>>(
        xh, xl, wdh, b_d, qhp, qlp, QSTR, CEMB,
        wlh, wll, b_lat, khp, klp, LDIM);
    // 3) attention (writes y-hi only)                <-- ncu-profiled slot
    attn_kernel<<<dim3(TSEQ/128, BATCH*NHEAD), 256, ATTN_SMEM>>>(
        qhp, qlp, khp, klp, yhp);
    // 4) pack W_proj (fp16 hi only)
    split_pack_h<<<dim3(QSTR/32, CEMB/32), tb>>>(W_proj, wph, QSTR, CEMB);
    // 5) out = y_hi @ Wp_hi + bias  (single-term fp16)
    gemm_f16x1<<<dim3(CEMB/128, MROWS/128), 256, GEMM_SMEM_P>>>(
        yhp, wph, b_proj, out, CEMB, CEMB);
}